// round 1
// baseline (speedup 1.0000x reference)
#include <cuda_runtime.h>
#include <cuda_bf16.h>
#include <mma.h>

using namespace nvcuda;

#define BATCH 8192
#define NREF  2048
#define KDIM  256
#define MT    64          // M-rows per CTA
#define NT    128         // refs per N-tile
#define LDS_K 264         // padded leading dim (halves) for S/R tiles
#define LDC   132         // padded leading dim (floats) for C scratch
#define NTILES (NREF / NT)

// Scratch (static device arrays — no dynamic allocation allowed)
__device__ __nv_bfloat16 g_Sbf[BATCH * KDIM];
__device__ __nv_bfloat16 g_Rbf[NREF * KDIM];

// ---------------------------------------------------------------------------
// Kernel 1: fp32 -> bf16 conversion of both inputs (values are exactly 0/1)
// ---------------------------------------------------------------------------
__global__ void convert_kernel(const float* __restrict__ S,
                               const float* __restrict__ R) {
    const int Sn4 = BATCH * KDIM / 4;
    const int Rn4 = NREF * KDIM / 4;
    int i = blockIdx.x * blockDim.x + threadIdx.x;
    if (i < Sn4) {
        float4 v = reinterpret_cast<const float4*>(S)[i];
        reinterpret_cast<__nv_bfloat162*>(g_Sbf)[2 * i]     = __floats2bfloat162_rn(v.x, v.y);
        reinterpret_cast<__nv_bfloat162*>(g_Sbf)[2 * i + 1] = __floats2bfloat162_rn(v.z, v.w);
    } else if (i < Sn4 + Rn4) {
        int j = i - Sn4;
        float4 v = reinterpret_cast<const float4*>(R)[j];
        reinterpret_cast<__nv_bfloat162*>(g_Rbf)[2 * j]     = __floats2bfloat162_rn(v.x, v.y);
        reinterpret_cast<__nv_bfloat162*>(g_Rbf)[2 * j + 1] = __floats2bfloat162_rn(v.z, v.w);
    }
}

// ---------------------------------------------------------------------------
// Kernel 2: per-CTA 64x2048x256 GEMM (wmma bf16) with fused min epilogue
//   dist[b,r] = cntS[b] + cntR[r] - 2*dot(S_b, R_r)
// ---------------------------------------------------------------------------
struct SmemT {
    __nv_bfloat16 S[MT * LDS_K];   // 33792 B
    __nv_bfloat16 R[NT * LDS_K];   // 67584 B
    float         C[MT * LDC];     // 33792 B
    float         cntS[MT];
    float         cntR[NT];
};

__global__ void __launch_bounds__(256, 1)
hamming_kernel(float* __restrict__ out) {
    extern __shared__ __align__(16) char smem_raw[];
    SmemT& sm = *reinterpret_cast<SmemT*>(smem_raw);

    const int tid = threadIdx.x;
    const int m0  = blockIdx.x * MT;

    // ---- Load S tile (bf16, vectorized 16B) ----
    {
        const float4* gs = reinterpret_cast<const float4*>(g_Sbf + (size_t)m0 * KDIM);
        const int vper = KDIM / 8;  // 32 float4 per row
        for (int i = tid; i < MT * vper; i += 256) {
            int r = i / vper, c = i % vper;
            reinterpret_cast<float4*>(&sm.S[r * LDS_K])[c] = gs[i];
        }
    }
    __syncthreads();

    // ---- Row popcounts of S tile ----
    if (tid < MT) {
        float s = 0.f;
        #pragma unroll 8
        for (int k = 0; k < KDIM; k++) s += __bfloat162float(sm.S[tid * LDS_K + k]);
        sm.cntS[tid] = s;
    }

    const int warpId = tid >> 5;
    const int wm = (warpId & 1) * 32;   // warp M-offset: 0 or 32
    const int wn = (warpId >> 1) * 32;  // warp N-offset: 0,32,64,96

    float runmin = 1e30f;
    const int row = tid >> 2;   // 0..63 (epilogue row ownership)
    const int q   = tid & 3;    // 4 threads cooperate per row

    for (int t = 0; t < NTILES; t++) {
        __syncthreads();  // prior epilogue / cntR readers done with R and C

        // ---- Load R tile (128 refs x 256 dims, bf16) ----
        {
            const float4* gr = reinterpret_cast<const float4*>(g_Rbf + (size_t)t * NT * KDIM);
            const int vper = KDIM / 8;
            for (int i = tid; i < NT * vper; i += 256) {
                int r = i / vper, c = i % vper;
                reinterpret_cast<float4*>(&sm.R[r * LDS_K])[c] = gr[i];
            }
        }
        __syncthreads();

        // ---- cntR for this tile (warps 0..3 only; visible after next sync) ----
        if (tid < NT) {
            float s = 0.f;
            #pragma unroll 8
            for (int k = 0; k < KDIM; k++) s += __bfloat162float(sm.R[tid * LDS_K + k]);
            sm.cntR[tid] = s;
        }

        // ---- MMA: each warp computes a 32x32 block of the 64x128 C tile ----
        wmma::fragment<wmma::accumulator, 16, 16, 16, float> c[2][2];
        #pragma unroll
        for (int i = 0; i < 2; i++)
            #pragma unroll
            for (int j = 0; j < 2; j++)
                wmma::fill_fragment(c[i][j], 0.0f);

        #pragma unroll
        for (int k0 = 0; k0 < KDIM; k0 += 16) {
            wmma::fragment<wmma::matrix_a, 16, 16, 16, __nv_bfloat16, wmma::row_major> a[2];
            wmma::fragment<wmma::matrix_b, 16, 16, 16, __nv_bfloat16, wmma::col_major> b[2];
            #pragma unroll
            for (int i = 0; i < 2; i++)
                wmma::load_matrix_sync(a[i], &sm.S[(wm + 16 * i) * LDS_K + k0], LDS_K);
            #pragma unroll
            for (int j = 0; j < 2; j++)
                wmma::load_matrix_sync(b[j], &sm.R[(wn + 16 * j) * LDS_K + k0], LDS_K);
            #pragma unroll
            for (int i = 0; i < 2; i++)
                #pragma unroll
                for (int j = 0; j < 2; j++)
                    wmma::mma_sync(c[i][j], a[i], b[j], c[i][j]);
        }

        #pragma unroll
        for (int i = 0; i < 2; i++)
            #pragma unroll
            for (int j = 0; j < 2; j++)
                wmma::store_matrix_sync(&sm.C[(wm + 16 * i) * LDC + wn + 16 * j],
                                        c[i][j], LDC, wmma::mem_row_major);
        __syncthreads();

        // ---- Fused min epilogue: dist - cntS = cntR[r] - 2*dot ----
        #pragma unroll 8
        for (int cc = q; cc < NT; cc += 4) {
            float d = sm.cntR[cc] - 2.0f * sm.C[row * LDC + cc];
            runmin = fminf(runmin, d);
        }
    }

    // combine the 4 threads per row
    runmin = fminf(runmin, __shfl_xor_sync(0xffffffffu, runmin, 1));
    runmin = fminf(runmin, __shfl_xor_sync(0xffffffffu, runmin, 2));
    if (q == 0) out[m0 + row] = sm.cntS[row] + runmin;
}

// ---------------------------------------------------------------------------
extern "C" void kernel_launch(void* const* d_in, const int* in_sizes, int n_in,
                              void* d_out, int out_size) {
    const float* states = (const float*)d_in[0];  // [8192, 256]
    const float* R      = (const float*)d_in[1];  // [2048, 256]
    float* out          = (float*)d_out;          // [8192]

    const int totalVec = (BATCH * KDIM + NREF * KDIM) / 4;
    convert_kernel<<<(totalVec + 255) / 256, 256>>>(states, R);

    cudaFuncSetAttribute(hamming_kernel,
                         cudaFuncAttributeMaxDynamicSharedMemorySize,
                         (int)sizeof(SmemT));
    hamming_kernel<<<BATCH / MT, 256, sizeof(SmemT)>>>(out);
}

// round 3
// speedup vs baseline: 1.0766x; 1.0766x over previous
#include <cuda_runtime.h>
#include <cstdint>

#define BATCH 8192
#define NREF  2048
#define KDIM  256
#define MT    128            // M rows per CTA
#define NQ    512            // refs per CTA (grid = 64 mtiles x 4 quarters)
#define NT    64             // refs per tile
#define NTILES (NQ / NT)     // 8
#define LDA   272            // padded row stride (bytes) for A in smem
#define LDB   272            // padded row stride (bytes) for B in smem

__device__ signed char g_S8[BATCH * KDIM];   // states as 0/1
__device__ signed char g_R8[NREF * KDIM];    // (1 - 2*R), values +-1
__device__ int         g_cntR[NREF];

struct Smem {
    signed char A[MT * LDA];        // 34816 B
    signed char B[2][NT * LDB];     // 34816 B
    int cntR[NQ];                   // 2048 B
};
#define SMEM_SZ (int)sizeof(Smem)

// ---------------------------------------------------------------------------
__device__ __forceinline__ uint32_t s2u(const void* p) {
    uint32_t a;
    asm("{ .reg .u64 t; cvta.to.shared.u64 t, %1; cvt.u32.u64 %0, t; }" : "=r"(a) : "l"(p));
    return a;
}
__device__ __forceinline__ void cpa16(uint32_t dst, const void* src) {
    asm volatile("cp.async.cg.shared.global [%0], [%1], 16;" :: "r"(dst), "l"(src));
}
template <int N>
__device__ __forceinline__ void cpwait() {
    asm volatile("cp.async.wait_group %0;" :: "n"(N) : "memory");
}
__device__ __forceinline__ void mma_s8(int* c, const uint32_t* a, uint32_t b0, uint32_t b1) {
    asm volatile(
        "mma.sync.aligned.m16n8k32.row.col.s32.s8.s8.s32 "
        "{%0,%1,%2,%3},{%4,%5,%6,%7},{%8,%9},{%0,%1,%2,%3};"
        : "+r"(c[0]), "+r"(c[1]), "+r"(c[2]), "+r"(c[3])
        : "r"(a[0]), "r"(a[1]), "r"(a[2]), "r"(a[3]), "r"(b0), "r"(b1));
}

// ---------------------------------------------------------------------------
// Kernel 1: fp32 -> s8. S stays 0/1; R becomes (1 - 2R) = +-1. Exact.
// ---------------------------------------------------------------------------
__global__ void convert_kernel(const float* __restrict__ S, const float* __restrict__ R) {
    const int Sn4 = BATCH * KDIM / 4;
    const int Rn4 = NREF * KDIM / 4;
    int i = blockIdx.x * blockDim.x + threadIdx.x;
    if (i < Sn4) {
        float4 v = reinterpret_cast<const float4*>(S)[i];
        char4 c;
        c.x = (signed char)v.x; c.y = (signed char)v.y;
        c.z = (signed char)v.z; c.w = (signed char)v.w;
        reinterpret_cast<char4*>(g_S8)[i] = c;
    } else if (i < Sn4 + Rn4) {
        int j = i - Sn4;
        float4 v = reinterpret_cast<const float4*>(R)[j];
        char4 c;
        c.x = (signed char)(1.f - 2.f * v.x); c.y = (signed char)(1.f - 2.f * v.y);
        c.z = (signed char)(1.f - 2.f * v.z); c.w = (signed char)(1.f - 2.f * v.w);
        reinterpret_cast<char4*>(g_R8)[j] = c;
    }
}

// ---------------------------------------------------------------------------
// Kernel 2: cntR[r] = sum_d R[r,d] (int), and init out (as int) to INT_MAX
// ---------------------------------------------------------------------------
__global__ void cntr_kernel(const float* __restrict__ R, int* __restrict__ outi) {
    int gtid = blockIdx.x * 256 + threadIdx.x;
    if (gtid < BATCH) outi[gtid] = 0x7FFFFFFF;
    int w = gtid >> 5, lane = gtid & 31;
    if (w < NREF) {
        int s = 0;
        #pragma unroll
        for (int k = lane; k < KDIM; k += 32) s += (int)R[w * KDIM + k];
        #pragma unroll
        for (int o = 16; o; o >>= 1) s += __shfl_xor_sync(0xffffffffu, s, o);
        if (lane == 0) g_cntR[w] = s;
    }
}

// ---------------------------------------------------------------------------
// Kernel 3: s8 IMMA GEMM, A in registers, B double-buffered cp.async,
//           fused integer min epilogue on accumulator fragments.
// ---------------------------------------------------------------------------
__device__ __forceinline__ void load_B(Smem& sm, int t, int buf, int quarter, int tid) {
    const signed char* src = g_R8 + ((size_t)(quarter * NQ + t * NT)) * KDIM;
    #pragma unroll
    for (int j = 0; j < 4; j++) {            // 1024 chunks of 16B / 256 threads
        int i = tid + j * 256;
        int r = i >> 4, c = i & 15;
        cpa16(s2u(&sm.B[buf][r * LDB + c * 16]), src + r * 256 + c * 16);
    }
    asm volatile("cp.async.commit_group;" ::: "memory");
}

__global__ void __launch_bounds__(256, 2) hamming_imma(int* __restrict__ outi) {
    extern __shared__ __align__(16) char smraw[];
    Smem& sm = *reinterpret_cast<Smem*>(smraw);

    const int tid  = threadIdx.x;
    const int wid  = tid >> 5;
    const int lane = tid & 31;
    const int g    = lane >> 2;    // group id (row within fragment)
    const int q    = lane & 3;     // quad id (col/k within fragment)
    const int mtile   = blockIdx.x >> 2;
    const int quarter = blockIdx.x & 3;

    // start streaming B tile 0 immediately
    load_B(sm, 0, 0, quarter, tid);

    // stage A (128 x 256 s8) coalesced into padded smem
    {
        const signed char* srcA = g_S8 + (size_t)mtile * MT * KDIM;
        #pragma unroll
        for (int j = 0; j < 8; j++) {        // 2048 chunks / 256 threads
            int i = tid + j * 256;
            int r = i >> 4, c = i & 15;
            *reinterpret_cast<float4*>(&sm.A[r * LDA + c * 16]) =
                *reinterpret_cast<const float4*>(&srcA[r * 256 + c * 16]);
        }
    }
    for (int i = tid; i < NQ; i += 256) sm.cntR[i] = g_cntR[quarter * NQ + i];
    __syncthreads();

    // load this warp's A fragments into registers (16 rows x 256 k)
    uint32_t a[8][4];
    {
        const int arow = wid * 16 + g;
        #pragma unroll
        for (int ks = 0; ks < 8; ks++) {
            int kb = ks * 32 + q * 4;
            a[ks][0] = *reinterpret_cast<const uint32_t*>(&sm.A[arow * LDA + kb]);
            a[ks][1] = *reinterpret_cast<const uint32_t*>(&sm.A[(arow + 8) * LDA + kb]);
            a[ks][2] = *reinterpret_cast<const uint32_t*>(&sm.A[arow * LDA + kb + 16]);
            a[ks][3] = *reinterpret_cast<const uint32_t*>(&sm.A[(arow + 8) * LDA + kb + 16]);
        }
    }

    int rmin0 = 0x7FFFFFFF, rmin1 = 0x7FFFFFFF;

    for (int t = 0; t < NTILES; t++) {
        if (t + 1 < NTILES) {
            load_B(sm, t + 1, (t + 1) & 1, quarter, tid);
            cpwait<1>();
        } else {
            cpwait<0>();
        }
        __syncthreads();

        const signed char* Bb = sm.B[t & 1];
        #pragma unroll
        for (int np = 0; np < 4; np++) {     // pairs of 8-col n-steps (16 refs)
            int c0[4] = {0, 0, 0, 0};
            int c1[4] = {0, 0, 0, 0};
            #pragma unroll
            for (int ks = 0; ks < 8; ks++) {
                int kb = ks * 32 + q * 4;
                uint32_t b00 = *reinterpret_cast<const uint32_t*>(&Bb[(np * 16 + g) * LDB + kb]);
                uint32_t b01 = *reinterpret_cast<const uint32_t*>(&Bb[(np * 16 + g) * LDB + kb + 16]);
                uint32_t b10 = *reinterpret_cast<const uint32_t*>(&Bb[(np * 16 + 8 + g) * LDB + kb]);
                uint32_t b11 = *reinterpret_cast<const uint32_t*>(&Bb[(np * 16 + 8 + g) * LDB + kb + 16]);
                mma_s8(c0, a[ks], b00, b01);
                mma_s8(c1, a[ks], b10, b11);
            }
            // epilogue: dist = acc + cntR[col]; integer min
            int colbase = t * 64 + np * 16 + q * 2;
            int2 cr0 = *reinterpret_cast<const int2*>(&sm.cntR[colbase]);
            int2 cr1 = *reinterpret_cast<const int2*>(&sm.cntR[colbase + 8]);
            rmin0 = min(rmin0, min(c0[0] + cr0.x, c0[1] + cr0.y));
            rmin1 = min(rmin1, min(c0[2] + cr0.x, c0[3] + cr0.y));
            rmin0 = min(rmin0, min(c1[0] + cr1.x, c1[1] + cr1.y));
            rmin1 = min(rmin1, min(c1[2] + cr1.x, c1[3] + cr1.y));
        }
        __syncthreads();
    }

    // combine the 4 threads (quads) covering the same rows
    rmin0 = min(rmin0, __shfl_xor_sync(0xffffffffu, rmin0, 1));
    rmin0 = min(rmin0, __shfl_xor_sync(0xffffffffu, rmin0, 2));
    rmin1 = min(rmin1, __shfl_xor_sync(0xffffffffu, rmin1, 1));
    rmin1 = min(rmin1, __shfl_xor_sync(0xffffffffu, rmin1, 2));
    if (q == 0) {
        atomicMin(&outi[mtile * MT + wid * 16 + g], rmin0);
        atomicMin(&outi[mtile * MT + wid * 16 + g + 8], rmin1);
    }
}

// ---------------------------------------------------------------------------
// Kernel 4: int -> float in place
// ---------------------------------------------------------------------------
__global__ void finalize_kernel(float* __restrict__ out) {
    int i = blockIdx.x * 256 + threadIdx.x;
    if (i < BATCH) {
        int v = reinterpret_cast<const int*>(out)[i];
        out[i] = (float)v;
    }
}

// ---------------------------------------------------------------------------
extern "C" void kernel_launch(void* const* d_in, const int* in_sizes, int n_in,
                              void* d_out, int out_size) {
    const float* states = (const float*)d_in[0];
    const float* R      = (const float*)d_in[1];
    float* out          = (float*)d_out;

    const int totalVec = (BATCH * KDIM + NREF * KDIM) / 4;
    convert_kernel<<<(totalVec + 255) / 256, 256>>>(states, R);
    cntr_kernel<<<256, 256>>>(R, (int*)out);

    cudaFuncSetAttribute(hamming_imma, cudaFuncAttributeMaxDynamicSharedMemorySize, SMEM_SZ);
    hamming_imma<<<(BATCH / MT) * 4, 256, SMEM_SZ>>>((int*)out);

    finalize_kernel<<<(BATCH + 255) / 256, 256>>>(out);
}

// round 4
// speedup vs baseline: 1.1197x; 1.0400x over previous
#include <cuda_runtime.h>
#include <cstdint>

#define BATCH 8192
#define NREF  2048
#define KDIM  256
#define MT    128            // M rows per CTA
#define NQ    512            // refs per CTA (grid = 64 mtiles x 4 quarters)
#define NT    64             // refs per tile
#define NTILES (NQ / NT)     // 8
#define LDA   272            // padded row stride (bytes)
#define LDB   272

__device__ signed char g_S8[BATCH * KDIM];   // states as 0/1
__device__ signed char g_R8[NREF * KDIM];    // (1 - 2*R), values +-1
__device__ int         g_cntR[NREF];

struct Smem {
    signed char A[MT * LDA];        // 34816 B
    signed char B[2][NT * LDB];     // 34816 B
    int cntR[NQ];                   // 2048 B
};
#define SMEM_SZ (int)sizeof(Smem)

// ---------------------------------------------------------------------------
__device__ __forceinline__ uint32_t s2u(const void* p) {
    uint32_t a;
    asm("{ .reg .u64 t; cvta.to.shared.u64 t, %1; cvt.u32.u64 %0, t; }" : "=r"(a) : "l"(p));
    return a;
}
__device__ __forceinline__ void cpa16(uint32_t dst, const void* src) {
    asm volatile("cp.async.cg.shared.global [%0], [%1], 16;" :: "r"(dst), "l"(src));
}
template <int N>
__device__ __forceinline__ void cpwait() {
    asm volatile("cp.async.wait_group %0;" :: "n"(N) : "memory");
}
__device__ __forceinline__ void mma_s8(int* c, const uint32_t* a, uint32_t b0, uint32_t b1) {
    asm volatile(
        "mma.sync.aligned.m16n8k32.row.col.s32.s8.s8.s32 "
        "{%0,%1,%2,%3},{%4,%5,%6,%7},{%8,%9},{%0,%1,%2,%3};"
        : "+r"(c[0]), "+r"(c[1]), "+r"(c[2]), "+r"(c[3])
        : "r"(a[0]), "r"(a[1]), "r"(a[2]), "r"(a[3]), "r"(b0), "r"(b1));
}

// ---------------------------------------------------------------------------
// Kernel 1 (prep): out init (+inf bits), fp32->s8 convert, cntR reduce.
// S stays 0/1; R becomes (1 - 2R) = +-1. All exact.
// ---------------------------------------------------------------------------
__global__ void prep_kernel(const float* __restrict__ S, const float* __restrict__ R,
                            int* __restrict__ outi) {
    const int Sn4 = BATCH * KDIM / 4;   // 524288
    const int Rn4 = NREF * KDIM / 4;    // 131072
    int i = blockIdx.x * 256 + threadIdx.x;

    if (i < BATCH) outi[i] = 0x7f800000;   // +inf (float bits)

    if (i < Sn4) {
        float4 v = reinterpret_cast<const float4*>(S)[i];
        char4 c;
        c.x = (signed char)v.x; c.y = (signed char)v.y;
        c.z = (signed char)v.z; c.w = (signed char)v.w;
        reinterpret_cast<char4*>(g_S8)[i] = c;
    } else if (i < Sn4 + Rn4) {
        int j = i - Sn4;
        float4 v = reinterpret_cast<const float4*>(R)[j];
        char4 c;
        c.x = (signed char)(1.f - 2.f * v.x); c.y = (signed char)(1.f - 2.f * v.y);
        c.z = (signed char)(1.f - 2.f * v.z); c.w = (signed char)(1.f - 2.f * v.w);
        reinterpret_cast<char4*>(g_R8)[j] = c;
    } else if (i < Sn4 + Rn4 + NREF * 32) {
        int t = i - (Sn4 + Rn4);
        int w = t >> 5, lane = t & 31;
        float s = 0.f;
        #pragma unroll
        for (int k = lane; k < KDIM; k += 32) s += R[w * KDIM + k];
        #pragma unroll
        for (int o = 16; o; o >>= 1) s += __shfl_xor_sync(0xffffffffu, s, o);
        if (lane == 0) g_cntR[w] = (int)s;
    }
}

// ---------------------------------------------------------------------------
// Kernel 2 (main): s8 IMMA GEMM, A in regs, B double-buffered cp.async,
// 8 independent accumulator chains per warp, fused min epilogue,
// float-bit atomicMin combine (no finalize pass).
// ---------------------------------------------------------------------------
__device__ __forceinline__ void load_B(Smem& sm, int t, int buf, int quarter, int tid) {
    const signed char* src = g_R8 + ((size_t)(quarter * NQ + t * NT)) * KDIM;
    #pragma unroll
    for (int j = 0; j < 4; j++) {            // 1024 x 16B / 256 threads
        int i = tid + j * 256;
        int r = i >> 4, c = i & 15;
        cpa16(s2u(&sm.B[buf][r * LDB + c * 16]), src + r * 256 + c * 16);
    }
    asm volatile("cp.async.commit_group;" ::: "memory");
}

__global__ void __launch_bounds__(256, 2) hamming_imma(int* __restrict__ outi) {
    extern __shared__ __align__(16) char smraw[];
    Smem& sm = *reinterpret_cast<Smem*>(smraw);

    const int tid  = threadIdx.x;
    const int wid  = tid >> 5;
    const int lane = tid & 31;
    const int g    = lane >> 2;    // row within fragment group
    const int q    = lane & 3;     // quad id
    const int mtile   = blockIdx.x >> 2;
    const int quarter = blockIdx.x & 3;

    load_B(sm, 0, 0, quarter, tid);          // group 0

    // stage A (128 x 256 s8), coalesced, padded rows
    {
        const signed char* srcA = g_S8 + (size_t)mtile * MT * KDIM;
        #pragma unroll
        for (int j = 0; j < 8; j++) {
            int i = tid + j * 256;
            int r = i >> 4, c = i & 15;
            *reinterpret_cast<float4*>(&sm.A[r * LDA + c * 16]) =
                *reinterpret_cast<const float4*>(&srcA[r * 256 + c * 16]);
        }
    }
    for (int i = tid; i < NQ; i += 256) sm.cntR[i] = g_cntR[quarter * NQ + i];
    __syncthreads();

    // this warp's A fragments (rows wid*16 .. +15, all 256 k) -> 32 regs
    uint32_t a[8][4];
    {
        const int arow = wid * 16 + g;
        #pragma unroll
        for (int ks = 0; ks < 8; ks++) {
            int kb = ks * 32 + q * 4;
            a[ks][0] = *reinterpret_cast<const uint32_t*>(&sm.A[arow * LDA + kb]);
            a[ks][1] = *reinterpret_cast<const uint32_t*>(&sm.A[(arow + 8) * LDA + kb]);
            a[ks][2] = *reinterpret_cast<const uint32_t*>(&sm.A[arow * LDA + kb + 16]);
            a[ks][3] = *reinterpret_cast<const uint32_t*>(&sm.A[(arow + 8) * LDA + kb + 16]);
        }
    }

    int rmin0 = 0x7FFFFFFF, rmin1 = 0x7FFFFFFF;

    for (int t = 0; t < NTILES; t++) {
        if (t + 1 < NTILES) {
            load_B(sm, t + 1, (t + 1) & 1, quarter, tid);
            cpwait<1>();
        } else {
            cpwait<0>();
        }
        __syncthreads();

        const signed char* Bb = sm.B[t & 1];
        int c[8][4];
        #pragma unroll
        for (int nb = 0; nb < 8; nb++)
            c[nb][0] = c[nb][1] = c[nb][2] = c[nb][3] = 0;

        #pragma unroll
        for (int ks = 0; ks < 8; ks++) {
            int kb = ks * 32 + q * 4;
            uint32_t b0[8], b1[8];
            #pragma unroll
            for (int nb = 0; nb < 8; nb++) {
                const signed char* bp = &Bb[(nb * 8 + g) * LDB + kb];
                b0[nb] = *reinterpret_cast<const uint32_t*>(bp);
                b1[nb] = *reinterpret_cast<const uint32_t*>(bp + 16);
            }
            // 8 independent accumulator chains -> latency fully hidden
            #pragma unroll
            for (int nb = 0; nb < 8; nb++) mma_s8(c[nb], a[ks], b0[nb], b1[nb]);
        }

        // fused epilogue: dist = acc + cntR[col]; integer min
        #pragma unroll
        for (int nb = 0; nb < 8; nb++) {
            int colbase = t * 64 + nb * 8 + q * 2;
            int2 cr = *reinterpret_cast<const int2*>(&sm.cntR[colbase]);
            rmin0 = min(rmin0, min(c[nb][0] + cr.x, c[nb][1] + cr.y));
            rmin1 = min(rmin1, min(c[nb][2] + cr.x, c[nb][3] + cr.y));
        }
        __syncthreads();
    }

    // combine quads (lanes with same rows)
    rmin0 = min(rmin0, __shfl_xor_sync(0xffffffffu, rmin0, 1));
    rmin0 = min(rmin0, __shfl_xor_sync(0xffffffffu, rmin0, 2));
    rmin1 = min(rmin1, __shfl_xor_sync(0xffffffffu, rmin1, 1));
    rmin1 = min(rmin1, __shfl_xor_sync(0xffffffffu, rmin1, 2));

    // combine quarters: float-bit atomicMin (all values >= 0 -> order-preserving)
    if (q == 0) {
        atomicMin(&outi[mtile * MT + wid * 16 + g],     __float_as_int((float)rmin0));
        atomicMin(&outi[mtile * MT + wid * 16 + g + 8], __float_as_int((float)rmin1));
    }
}

// ---------------------------------------------------------------------------
extern "C" void kernel_launch(void* const* d_in, const int* in_sizes, int n_in,
                              void* d_out, int out_size) {
    const float* states = (const float*)d_in[0];
    const float* R      = (const float*)d_in[1];
    int* outi           = (int*)d_out;

    const int prepThreads = BATCH * KDIM / 4 + NREF * KDIM / 4 + NREF * 32;
    prep_kernel<<<(prepThreads + 255) / 256, 256>>>(states, R, outi);

    cudaFuncSetAttribute(hamming_imma, cudaFuncAttributeMaxDynamicSharedMemorySize, SMEM_SZ);
    hamming_imma<<<(BATCH / MT) * 4, 256, SMEM_SZ>>>(outi);
}

// round 5
// speedup vs baseline: 2.2193x; 1.9820x over previous
#include <cuda_runtime.h>
#include <cuda_bf16.h>
#include <cstdint>

#define BATCH 8192
#define NREF  2048
#define KDIM  256
#define MT    128             // M rows per CTA
#define NQ    512             // refs per CTA (grid = 64 mtiles x 4 quarters)
#define NT    64              // refs per tile
#define NTILES (NQ / NT)      // 8
#define ROWB  512             // bytes per row (256 bf16)
#define LDB   528             // padded smem row stride (bytes)

__device__ __nv_bfloat16 g_Sbf[BATCH * KDIM];   // states as 0/1
__device__ __nv_bfloat16 g_Rbf[NREF * KDIM];    // (1 - 2R) = +-1
__device__ float         g_cntR[NREF];

struct Smem {
    char  B[2][NT * LDB];     // 2 x 33792 B
    float cntR[NQ];           // 2048 B
};
#define SMEM_SZ (int)sizeof(Smem)

// ---------------------------------------------------------------------------
__device__ __forceinline__ uint32_t s2u(const void* p) {
    uint32_t a;
    asm("{ .reg .u64 t; cvta.to.shared.u64 t, %1; cvt.u32.u64 %0, t; }" : "=r"(a) : "l"(p));
    return a;
}
__device__ __forceinline__ void cpa16(uint32_t dst, const void* src) {
    asm volatile("cp.async.cg.shared.global [%0], [%1], 16;" :: "r"(dst), "l"(src));
}
template <int N>
__device__ __forceinline__ void cpwait() {
    asm volatile("cp.async.wait_group %0;" :: "n"(N) : "memory");
}
__device__ __forceinline__ void mma_bf16(float* c, const uint32_t* a, uint32_t b0, uint32_t b1) {
    asm volatile(
        "mma.sync.aligned.m16n8k16.row.col.f32.bf16.bf16.f32 "
        "{%0,%1,%2,%3},{%4,%5,%6,%7},{%8,%9},{%0,%1,%2,%3};"
        : "+f"(c[0]), "+f"(c[1]), "+f"(c[2]), "+f"(c[3])
        : "r"(a[0]), "r"(a[1]), "r"(a[2]), "r"(a[3]), "r"(b0), "r"(b1));
}

// ---------------------------------------------------------------------------
// Kernel 1 (prep): out init (+inf bits), fp32->bf16 convert, cntR reduce.
// S stays 0/1 (exact in bf16); R becomes (1-2R) = +-1 (exact).
// ---------------------------------------------------------------------------
__global__ void prep_kernel(const float* __restrict__ S, const float* __restrict__ R,
                            int* __restrict__ outi) {
    const int Sn4 = BATCH * KDIM / 4;   // 524288
    const int Rn4 = NREF * KDIM / 4;    // 131072
    int i = blockIdx.x * 256 + threadIdx.x;

    if (i < BATCH) outi[i] = 0x7f800000;   // +inf bits

    if (i < Sn4) {
        float4 v = reinterpret_cast<const float4*>(S)[i];
        reinterpret_cast<__nv_bfloat162*>(g_Sbf)[2 * i]     = __floats2bfloat162_rn(v.x, v.y);
        reinterpret_cast<__nv_bfloat162*>(g_Sbf)[2 * i + 1] = __floats2bfloat162_rn(v.z, v.w);
    } else if (i < Sn4 + Rn4) {
        int j = i - Sn4;
        float4 v = reinterpret_cast<const float4*>(R)[j];
        reinterpret_cast<__nv_bfloat162*>(g_Rbf)[2 * j] =
            __floats2bfloat162_rn(1.f - 2.f * v.x, 1.f - 2.f * v.y);
        reinterpret_cast<__nv_bfloat162*>(g_Rbf)[2 * j + 1] =
            __floats2bfloat162_rn(1.f - 2.f * v.z, 1.f - 2.f * v.w);
    } else if (i < Sn4 + Rn4 + NREF * 32) {
        int t = i - (Sn4 + Rn4);
        int w = t >> 5, lane = t & 31;
        float s = 0.f;
        #pragma unroll
        for (int k = lane; k < KDIM; k += 32) s += R[w * KDIM + k];
        #pragma unroll
        for (int o = 16; o; o >>= 1) s += __shfl_xor_sync(0xffffffffu, s, o);
        if (lane == 0) g_cntR[w] = s;
    }
}

// ---------------------------------------------------------------------------
// Kernel 2 (main): bf16 HMMA GEMM. A fragments in registers (loaded from
// global once), B double-buffered via cp.async, 8 independent accumulator
// chains, fused min epilogue, float-bit atomicMin combine.
// ---------------------------------------------------------------------------
__device__ __forceinline__ void load_B(Smem& sm, int t, int buf, int quarter, int tid) {
    const char* src = (const char*)g_Rbf + ((size_t)(quarter * NQ + t * NT)) * ROWB;
    #pragma unroll
    for (int j = 0; j < 8; j++) {            // 2048 x 16B chunks / 256 threads
        int i = tid + j * 256;
        int r = i >> 5, c = i & 31;          // 32 chunks per 512B row
        cpa16(s2u(&sm.B[buf][r * LDB + c * 16]), src + (size_t)r * ROWB + c * 16);
    }
    asm volatile("cp.async.commit_group;" ::: "memory");
}

__global__ void __launch_bounds__(256, 2) hamming_hmma(int* __restrict__ outi) {
    extern __shared__ __align__(16) char smraw[];
    Smem& sm = *reinterpret_cast<Smem*>(smraw);

    const int tid  = threadIdx.x;
    const int wid  = tid >> 5;
    const int lane = tid & 31;
    const int g    = lane >> 2;    // fragment row group
    const int q    = lane & 3;     // quad id
    const int mtile   = blockIdx.x >> 2;
    const int quarter = blockIdx.x & 3;

    load_B(sm, 0, 0, quarter, tid);                       // tile 0 in flight

    // A fragments straight from global: rows mtile*128 + wid*16 + {g, g+8}
    uint32_t a[16][4];
    {
        const char* rowLo = (const char*)g_Sbf + ((size_t)(mtile * MT + wid * 16 + g)) * ROWB;
        const char* rowHi = rowLo + 8 * ROWB;
        #pragma unroll
        for (int ks = 0; ks < 16; ks++) {
            int base = ks * 32 + q * 4;
            a[ks][0] = *reinterpret_cast<const uint32_t*>(rowLo + base);
            a[ks][1] = *reinterpret_cast<const uint32_t*>(rowHi + base);
            a[ks][2] = *reinterpret_cast<const uint32_t*>(rowLo + base + 16);
            a[ks][3] = *reinterpret_cast<const uint32_t*>(rowHi + base + 16);
        }
    }
    for (int i = tid; i < NQ; i += 256) sm.cntR[i] = g_cntR[quarter * NQ + i];

    float rmin0 = __int_as_float(0x7f800000);
    float rmin1 = rmin0;

    for (int t = 0; t < NTILES; t++) {
        if (t + 1 < NTILES) {
            load_B(sm, t + 1, (t + 1) & 1, quarter, tid);
            cpwait<1>();
        } else {
            cpwait<0>();
        }
        __syncthreads();

        const char* Bb = sm.B[t & 1];
        float c[8][4];
        #pragma unroll
        for (int nb = 0; nb < 8; nb++)
            c[nb][0] = c[nb][1] = c[nb][2] = c[nb][3] = 0.f;

        #pragma unroll
        for (int ks = 0; ks < 16; ks++) {
            int kb = ks * 32 + q * 4;
            #pragma unroll
            for (int grp = 0; grp < 2; grp++) {          // 2 groups of 4 nb
                uint32_t b0[4], b1[4];
                #pragma unroll
                for (int u = 0; u < 4; u++) {
                    const char* bp = &Bb[((grp * 4 + u) * 8 + g) * LDB + kb];
                    b0[u] = *reinterpret_cast<const uint32_t*>(bp);
                    b1[u] = *reinterpret_cast<const uint32_t*>(bp + 16);
                }
                #pragma unroll
                for (int u = 0; u < 4; u++)
                    mma_bf16(c[grp * 4 + u], a[ks], b0[u], b1[u]);
            }
        }

        // fused epilogue: dist = acc + cntR[col]; min
        #pragma unroll
        for (int nb = 0; nb < 8; nb++) {
            int colbase = t * 64 + nb * 8 + q * 2;
            float2 cr = *reinterpret_cast<const float2*>(&sm.cntR[colbase]);
            rmin0 = fminf(rmin0, fminf(c[nb][0] + cr.x, c[nb][1] + cr.y));
            rmin1 = fminf(rmin1, fminf(c[nb][2] + cr.x, c[nb][3] + cr.y));
        }
        __syncthreads();
    }

    // combine quads (lanes sharing the same rows)
    rmin0 = fminf(rmin0, __shfl_xor_sync(0xffffffffu, rmin0, 1));
    rmin0 = fminf(rmin0, __shfl_xor_sync(0xffffffffu, rmin0, 2));
    rmin1 = fminf(rmin1, __shfl_xor_sync(0xffffffffu, rmin1, 1));
    rmin1 = fminf(rmin1, __shfl_xor_sync(0xffffffffu, rmin1, 2));

    // combine quarters: int atomicMin on float bits (all values >= 0)
    if (q == 0) {
        atomicMin(&outi[mtile * MT + wid * 16 + g],     __float_as_int(rmin0));
        atomicMin(&outi[mtile * MT + wid * 16 + g + 8], __float_as_int(rmin1));
    }
}

// ---------------------------------------------------------------------------
extern "C" void kernel_launch(void* const* d_in, const int* in_sizes, int n_in,
                              void* d_out, int out_size) {
    const float* states = (const float*)d_in[0];
    const float* R      = (const float*)d_in[1];
    int* outi           = (int*)d_out;

    const int prepThreads = BATCH * KDIM / 4 + NREF * KDIM / 4 + NREF * 32;
    prep_kernel<<<(prepThreads + 255) / 256, 256>>>(states, R, outi);

    cudaFuncSetAttribute(hamming_hmma, cudaFuncAttributeMaxDynamicSharedMemorySize, SMEM_SZ);
    hamming_hmma<<<(BATCH / MT) * 4, 256, SMEM_SZ>>>(outi);
}

// round 6
// speedup vs baseline: 2.4388x; 1.0989x over previous
#include <cuda_runtime.h>
#include <cuda_bf16.h>
#include <cstdint>

#define BATCH 8192
#define NREF  2048
#define KDIM  256
#define MT    128             // M rows per CTA (4 warps x 32 rows)
#define NQ    512             // refs per CTA (grid = 64 mtiles x 4 quarters)
#define NT    64              // refs per tile
#define NTILES (NQ / NT)      // 8
#define ROWB  512             // bytes per bf16 row (256 bf16)
#define LDB   528             // padded smem row stride (bytes)

__device__ __nv_bfloat16 g_Rbf[NREF * KDIM];    // (1 - 2R) = +-1
__device__ float         g_cntR[NREF];

struct Smem {
    char  B[2][NT * LDB];     // 2 x 33792 B
    float cntR[NQ];           // 2048 B
};
#define SMEM_SZ (int)sizeof(Smem)

// ---------------------------------------------------------------------------
__device__ __forceinline__ uint32_t s2u(const void* p) {
    uint32_t a;
    asm("{ .reg .u64 t; cvta.to.shared.u64 t, %1; cvt.u32.u64 %0, t; }" : "=r"(a) : "l"(p));
    return a;
}
__device__ __forceinline__ void cpa16(uint32_t dst, const void* src) {
    asm volatile("cp.async.cg.shared.global [%0], [%1], 16;" :: "r"(dst), "l"(src));
}
template <int N>
__device__ __forceinline__ void cpwait() {
    asm volatile("cp.async.wait_group %0;" :: "n"(N) : "memory");
}
__device__ __forceinline__ void mma_bf16(float* c, const uint32_t* a, uint32_t b0, uint32_t b1) {
    asm volatile(
        "mma.sync.aligned.m16n8k16.row.col.f32.bf16.bf16.f32 "
        "{%0,%1,%2,%3},{%4,%5,%6,%7},{%8,%9},{%0,%1,%2,%3};"
        : "+f"(c[0]), "+f"(c[1]), "+f"(c[2]), "+f"(c[3])
        : "r"(a[0]), "r"(a[1]), "r"(a[2]), "r"(a[3]), "r"(b0), "r"(b1));
}
__device__ __forceinline__ uint32_t packbf(float x, float y) {
    __nv_bfloat162 h = __floats2bfloat162_rn(x, y);
    return *reinterpret_cast<uint32_t*>(&h);
}

// ---------------------------------------------------------------------------
// Kernel 1 (prep): out init, R fp32 -> bf16 (1-2R), cntR reduce. All exact.
// ---------------------------------------------------------------------------
__global__ void prep_kernel(const float* __restrict__ R, int* __restrict__ outi) {
    const int Rn4 = NREF * KDIM / 4;    // 131072
    int i = blockIdx.x * 256 + threadIdx.x;

    if (i < BATCH) outi[i] = 0x7f800000;   // +inf bits

    if (i < Rn4) {
        float4 v = reinterpret_cast<const float4*>(R)[i];
        reinterpret_cast<__nv_bfloat162*>(g_Rbf)[2 * i] =
            __floats2bfloat162_rn(1.f - 2.f * v.x, 1.f - 2.f * v.y);
        reinterpret_cast<__nv_bfloat162*>(g_Rbf)[2 * i + 1] =
            __floats2bfloat162_rn(1.f - 2.f * v.z, 1.f - 2.f * v.w);
    } else if (i < Rn4 + NREF * 32) {
        int t = i - Rn4;
        int w = t >> 5, lane = t & 31;
        float s = 0.f;
        #pragma unroll
        for (int k = lane; k < KDIM; k += 32) s += R[w * KDIM + k];
        #pragma unroll
        for (int o = 16; o; o >>= 1) s += __shfl_xor_sync(0xffffffffu, s, o);
        if (lane == 0) g_cntR[w] = s;
    }
}

// ---------------------------------------------------------------------------
// Kernel 2 (main): bf16 HMMA. Each warp owns 32 M-rows (2 A-tiles) so every
// B fragment feeds 2 HMMAs (halves smem crossbar pressure per MMA).
// A fragments converted from the float input directly into registers.
// ---------------------------------------------------------------------------
__device__ __forceinline__ void load_B(Smem& sm, int t, int buf, int quarter, int tid) {
    const char* src = (const char*)g_Rbf + ((size_t)(quarter * NQ + t * NT)) * ROWB;
    #pragma unroll
    for (int j = 0; j < 16; j++) {           // 2048 x 16B chunks / 128 threads
        int i = tid + j * 128;
        int r = i >> 5, c = i & 31;
        cpa16(s2u(&sm.B[buf][r * LDB + c * 16]), src + (size_t)r * ROWB + c * 16);
    }
    asm volatile("cp.async.commit_group;" ::: "memory");
}

__global__ void __launch_bounds__(128, 2) hamming_hmma(const float* __restrict__ S,
                                                       int* __restrict__ outi) {
    extern __shared__ __align__(16) char smraw[];
    Smem& sm = *reinterpret_cast<Smem*>(smraw);

    const int tid  = threadIdx.x;
    const int wid  = tid >> 5;
    const int lane = tid & 31;
    const int g    = lane >> 2;
    const int q    = lane & 3;
    const int mtile   = blockIdx.x >> 2;
    const int quarter = blockIdx.x & 3;

    load_B(sm, 0, 0, quarter, tid);                       // tile 0 in flight

    // A fragments from float S: 2 m16-tiles x 16 k-steps x 4 regs
    uint32_t a[2][16][4];
    {
        #pragma unroll
        for (int mt = 0; mt < 2; mt++) {
            const float* rowLo = S + ((size_t)(mtile * MT + wid * 32 + mt * 16 + g)) * KDIM;
            const float* rowHi = rowLo + 8 * KDIM;
            #pragma unroll
            for (int ks = 0; ks < 16; ks++) {
                int k0 = ks * 16 + q * 2;
                float2 lo0 = *reinterpret_cast<const float2*>(rowLo + k0);
                float2 hi0 = *reinterpret_cast<const float2*>(rowHi + k0);
                float2 lo1 = *reinterpret_cast<const float2*>(rowLo + k0 + 8);
                float2 hi1 = *reinterpret_cast<const float2*>(rowHi + k0 + 8);
                a[mt][ks][0] = packbf(lo0.x, lo0.y);
                a[mt][ks][1] = packbf(hi0.x, hi0.y);
                a[mt][ks][2] = packbf(lo1.x, lo1.y);
                a[mt][ks][3] = packbf(hi1.x, hi1.y);
            }
        }
    }
    for (int i = tid; i < NQ; i += 128) sm.cntR[i] = g_cntR[quarter * NQ + i];

    float rmin[2][2] = {{__int_as_float(0x7f800000), __int_as_float(0x7f800000)},
                        {__int_as_float(0x7f800000), __int_as_float(0x7f800000)}};

    for (int t = 0; t < NTILES; t++) {
        if (t + 1 < NTILES) {
            load_B(sm, t + 1, (t + 1) & 1, quarter, tid);
            cpwait<1>();
        } else {
            cpwait<0>();
        }
        __syncthreads();

        const char* Bb = sm.B[t & 1];

        #pragma unroll
        for (int grp = 0; grp < 2; grp++) {               // 2 groups of 4 n-blocks
            float c[2][4][4];
            #pragma unroll
            for (int mt = 0; mt < 2; mt++)
                #pragma unroll
                for (int u = 0; u < 4; u++)
                    c[mt][u][0] = c[mt][u][1] = c[mt][u][2] = c[mt][u][3] = 0.f;

            #pragma unroll
            for (int ks = 0; ks < 16; ks++) {
                int kb = ks * 32 + q * 4;
                uint32_t b0[4], b1[4];
                #pragma unroll
                for (int u = 0; u < 4; u++) {
                    const char* bp = &Bb[((grp * 4 + u) * 8 + g) * LDB + kb];
                    b0[u] = *reinterpret_cast<const uint32_t*>(bp);
                    b1[u] = *reinterpret_cast<const uint32_t*>(bp + 16);
                }
                // each B fragment feeds both A tiles: 8 HMMA per 8 LDS.32
                #pragma unroll
                for (int u = 0; u < 4; u++) {
                    mma_bf16(c[0][u], a[0][ks], b0[u], b1[u]);
                    mma_bf16(c[1][u], a[1][ks], b0[u], b1[u]);
                }
            }

            // fused epilogue for this group
            #pragma unroll
            for (int u = 0; u < 4; u++) {
                int colbase = t * 64 + (grp * 4 + u) * 8 + q * 2;
                float2 cr = *reinterpret_cast<const float2*>(&sm.cntR[colbase]);
                #pragma unroll
                for (int mt = 0; mt < 2; mt++) {
                    rmin[mt][0] = fminf(rmin[mt][0],
                                        fminf(c[mt][u][0] + cr.x, c[mt][u][1] + cr.y));
                    rmin[mt][1] = fminf(rmin[mt][1],
                                        fminf(c[mt][u][2] + cr.x, c[mt][u][3] + cr.y));
                }
            }
        }
        __syncthreads();
    }

    // combine quads; then quarters via int atomicMin on float bits (all >= 0)
    #pragma unroll
    for (int mt = 0; mt < 2; mt++) {
        #pragma unroll
        for (int h = 0; h < 2; h++) {
            float v = rmin[mt][h];
            v = fminf(v, __shfl_xor_sync(0xffffffffu, v, 1));
            v = fminf(v, __shfl_xor_sync(0xffffffffu, v, 2));
            if (q == 0)
                atomicMin(&outi[mtile * MT + wid * 32 + mt * 16 + h * 8 + g],
                          __float_as_int(v));
        }
    }
}

// ---------------------------------------------------------------------------
extern "C" void kernel_launch(void* const* d_in, const int* in_sizes, int n_in,
                              void* d_out, int out_size) {
    const float* states = (const float*)d_in[0];
    const float* R      = (const float*)d_in[1];
    int* outi           = (int*)d_out;

    const int prepThreads = NREF * KDIM / 4 + NREF * 32;   // 196608
    prep_kernel<<<(prepThreads + 255) / 256, 256>>>(R, outi);

    cudaFuncSetAttribute(hamming_hmma, cudaFuncAttributeMaxDynamicSharedMemorySize, SMEM_SZ);
    hamming_hmma<<<(BATCH / MT) * 4, 128, SMEM_SZ>>>(states, outi);
}